// round 1
// baseline (speedup 1.0000x reference)
#include <cuda_runtime.h>
#include <math.h>

#define Bz   4
#define Nq   4097
#define CDIM 384
#define HEADS 8
#define HD   48
#define Msr  513

// ---------------- scratch (static device globals; no allocs allowed) --------
__device__ float g_q   [(size_t)Bz * Nq  * CDIM];   // q projection  [B,N,C]
__device__ float g_attn[(size_t)Bz * Nq  * CDIM];   // attention out [B,N,C]
__device__ float g_xr  [(size_t)Bz * Msr * CDIM];   // reduced+LN tokens
__device__ float g_kv  [(size_t)Bz * Msr * 2 * CDIM]; // kv projection

// ---------------- fused depthwise-conv(2x2x2,s2) + CLS + LayerNorm ----------
__global__ __launch_bounds__(384)
void reduce_ln_kernel(const float* __restrict__ x,
                      const float* __restrict__ sr_w,
                      const float* __restrict__ sr_b,
                      const float* __restrict__ ln_g,
                      const float* __restrict__ ln_b) {
    int m = blockIdx.x;          // 0..512 (0 = CLS)
    int b = blockIdx.y;
    int c = threadIdx.x;         // 384 channels

    float val;
    if (m == 0) {
        val = x[(size_t)(b * Nq) * CDIM + c];
    } else {
        int p  = m - 1;
        int z0 = p >> 6, z1 = (p >> 3) & 7, z2 = p & 7;
        int base = 1 + (2 * z0) * 256 + (2 * z1) * 16 + (2 * z2);
        float acc = sr_b[c];
#pragma unroll
        for (int i = 0; i < 2; i++)
#pragma unroll
            for (int j = 0; j < 2; j++)
#pragma unroll
                for (int k = 0; k < 2; k++) {
                    int tok = base + i * 256 + j * 16 + k;
                    acc = fmaf(x[(size_t)(b * Nq + tok) * CDIM + c],
                               sr_w[c * 8 + i * 4 + j * 2 + k], acc);
                }
        val = acc;
    }

    // block reduce mean / meansq over 384 threads (12 warps)
    __shared__ float s_sum[12], s_sq[12];
    float v1 = val, v2 = val * val;
#pragma unroll
    for (int off = 16; off > 0; off >>= 1) {
        v1 += __shfl_xor_sync(0xffffffffu, v1, off);
        v2 += __shfl_xor_sync(0xffffffffu, v2, off);
    }
    int warp = c >> 5, lane = c & 31;
    if (lane == 0) { s_sum[warp] = v1; s_sq[warp] = v2; }
    __syncthreads();
    float tot = 0.f, totsq = 0.f;
#pragma unroll
    for (int w = 0; w < 12; w++) { tot += s_sum[w]; totsq += s_sq[w]; }
    float mu  = tot * (1.0f / CDIM);
    float var = totsq * (1.0f / CDIM) - mu * mu;
    float y = (val - mu) * rsqrtf(var + 1e-5f) * ln_g[c] + ln_b[c];
    g_xr[(size_t)(b * Msr + m) * CDIM + c] = y;
}

// ---------------- tiled fp32 GEMM:  C[M,N] = A[M,K] @ W[N,K]^T (+bias) ------
template<bool HAS_BIAS>
__global__ __launch_bounds__(256)
void gemm64_kernel(const float* __restrict__ A, const float* __restrict__ W,
                   const float* __restrict__ bias, float* __restrict__ C,
                   int Mdim, int Ndim, int Kdim) {
    const int BM = 64, BN = 64, BK = 16;
    __shared__ float As[BK][BM];
    __shared__ float Ws[BK][BN];
    int tid = threadIdx.x;
    int tx = tid & 15, ty = tid >> 4;
    int m0 = blockIdx.y * BM, n0 = blockIdx.x * BN;

    float acc[4][4] = {};
    int lrow = tid >> 2;
    int lk   = (tid & 3) * 4;

    for (int k0 = 0; k0 < Kdim; k0 += BK) {
        float4 av = make_float4(0.f, 0.f, 0.f, 0.f);
        if (m0 + lrow < Mdim)
            av = *(const float4*)&A[(size_t)(m0 + lrow) * Kdim + k0 + lk];
        As[lk + 0][lrow] = av.x; As[lk + 1][lrow] = av.y;
        As[lk + 2][lrow] = av.z; As[lk + 3][lrow] = av.w;
        float4 wv = *(const float4*)&W[(size_t)(n0 + lrow) * Kdim + k0 + lk];
        Ws[lk + 0][lrow] = wv.x; Ws[lk + 1][lrow] = wv.y;
        Ws[lk + 2][lrow] = wv.z; Ws[lk + 3][lrow] = wv.w;
        __syncthreads();
#pragma unroll
        for (int kk = 0; kk < BK; kk++) {
            float4 a = *(const float4*)&As[kk][ty * 4];
            float4 w = *(const float4*)&Ws[kk][tx * 4];
            float avr[4] = {a.x, a.y, a.z, a.w};
            float wvr[4] = {w.x, w.y, w.z, w.w};
#pragma unroll
            for (int i = 0; i < 4; i++)
#pragma unroll
                for (int j = 0; j < 4; j++)
                    acc[i][j] = fmaf(avr[i], wvr[j], acc[i][j]);
        }
        __syncthreads();
    }

#pragma unroll
    for (int i = 0; i < 4; i++) {
        int m = m0 + ty * 4 + i;
        if (m < Mdim) {
            float4 o;
            int n = n0 + tx * 4;
            o.x = acc[i][0]; o.y = acc[i][1]; o.z = acc[i][2]; o.w = acc[i][3];
            if (HAS_BIAS) {
                o.x += bias[n + 0]; o.y += bias[n + 1];
                o.z += bias[n + 2]; o.w += bias[n + 3];
            }
            *(float4*)&C[(size_t)m * Ndim + n] = o;
        }
    }
}

// ---------------- fused flash-style attention -------------------------------
// one thread per query; K/V chunks staged in smem; online softmax (8-key groups)
#define MT 124
__global__ __launch_bounds__(256)
void attn_kernel() {
    __shared__ float ks[MT][HD];
    __shared__ float vs[MT][HD];
    int tid = threadIdx.x;
    int h = blockIdx.y, b = blockIdx.z;
    int n = blockIdx.x * 256 + tid;
    bool valid = (n < Nq);

    float qreg[HD];
    if (valid) {
        const float* qp = &g_q[(size_t)(b * Nq + n) * CDIM + h * HD];
#pragma unroll
        for (int d = 0; d < HD; d += 4) {
            float4 t = *(const float4*)&qp[d];
            qreg[d] = t.x; qreg[d + 1] = t.y; qreg[d + 2] = t.z; qreg[d + 3] = t.w;
        }
    } else {
#pragma unroll
        for (int d = 0; d < HD; d++) qreg[d] = 0.f;
    }

    float acc[HD] = {};
    float mx = -1e30f, denom = 0.f;
    const float scale = rsqrtf((float)HD);

    for (int m0 = 0; m0 < Msr; m0 += MT) {
        int mv = min(MT, Msr - m0);
        // cooperative K/V chunk load
        for (int u = tid; u < MT * (HD / 4); u += 256) {
            int mm = u / (HD / 4);
            int d4 = (u % (HD / 4)) * 4;
            if (mm < mv) {
                size_t base = (size_t)(b * Msr + m0 + mm) * (2 * CDIM) + h * HD + d4;
                *(float4*)&ks[mm][d4] = *(const float4*)&g_kv[base];
                *(float4*)&vs[mm][d4] = *(const float4*)&g_kv[base + CDIM];
            }
        }
        __syncthreads();

        if (valid) {
            int g = 0;
            for (; g + 8 <= mv; g += 8) {
                float sreg[8];
#pragma unroll
                for (int e = 0; e < 8; e++) {
                    float s = 0.f;
#pragma unroll
                    for (int d = 0; d < HD; d++) s = fmaf(qreg[d], ks[g + e][d], s);
                    sreg[e] = s * scale;
                }
                float gm = sreg[0];
#pragma unroll
                for (int e = 1; e < 8; e++) gm = fmaxf(gm, sreg[e]);
                float nm = fmaxf(mx, gm);
                float corr = __expf(mx - nm);
                mx = nm;
                denom *= corr;
#pragma unroll
                for (int d = 0; d < HD; d++) acc[d] *= corr;
#pragma unroll
                for (int e = 0; e < 8; e++) {
                    float p = __expf(sreg[e] - nm);
                    denom += p;
#pragma unroll
                    for (int d = 0; d < HD; d++) acc[d] = fmaf(p, vs[g + e][d], acc[d]);
                }
            }
            for (; g < mv; g++) {   // tail
                float s = 0.f;
#pragma unroll
                for (int d = 0; d < HD; d++) s = fmaf(qreg[d], ks[g][d], s);
                s *= scale;
                float nm = fmaxf(mx, s);
                float corr = __expf(mx - nm);
                float p = __expf(s - nm);
                mx = nm;
                denom = denom * corr + p;
#pragma unroll
                for (int d = 0; d < HD; d++) acc[d] = fmaf(p, vs[g][d], acc[d] * corr);
            }
        }
        __syncthreads();
    }

    if (valid) {
        float inv = 1.f / denom;
        float* op = &g_attn[(size_t)(b * Nq + n) * CDIM + h * HD];
#pragma unroll
        for (int d = 0; d < HD; d += 4) {
            float4 t = make_float4(acc[d] * inv, acc[d + 1] * inv,
                                   acc[d + 2] * inv, acc[d + 3] * inv);
            *(float4*)&op[d] = t;
        }
    }
}

// ---------------- launcher ---------------------------------------------------
extern "C" void kernel_launch(void* const* d_in, const int* in_sizes, int n_in,
                              void* d_out, int out_size) {
    const float* x      = (const float*)d_in[0];
    const float* q_w    = (const float*)d_in[1];
    const float* kv_w   = (const float*)d_in[2];
    const float* proj_w = (const float*)d_in[3];
    const float* proj_b = (const float*)d_in[4];
    const float* sr_w   = (const float*)d_in[5];
    const float* sr_b   = (const float*)d_in[6];
    const float* ln_g   = (const float*)d_in[7];
    const float* ln_b   = (const float*)d_in[8];
    float* out = (float*)d_out;

    float *qb, *xrb, *kvb, *atb;
    cudaGetSymbolAddress((void**)&qb,  g_q);
    cudaGetSymbolAddress((void**)&xrb, g_xr);
    cudaGetSymbolAddress((void**)&kvb, g_kv);
    cudaGetSymbolAddress((void**)&atb, g_attn);

    const int Mq = Bz * Nq;        // 16388
    const int Mr = Bz * Msr;       // 2052

    // 1. reduced tokens + LN
    reduce_ln_kernel<<<dim3(Msr, Bz), 384>>>(x, sr_w, sr_b, ln_g, ln_b);
    // 2. kv projection: [Mr,384] @ [768,384]^T
    gemm64_kernel<false><<<dim3((2 * CDIM) / 64, (Mr + 63) / 64), 256>>>(
        xrb, kv_w, nullptr, kvb, Mr, 2 * CDIM, CDIM);
    // 3. q projection: [Mq,384] @ [384,384]^T
    gemm64_kernel<false><<<dim3(CDIM / 64, (Mq + 63) / 64), 256>>>(
        x, q_w, nullptr, qb, Mq, CDIM, CDIM);
    // 4. attention
    attn_kernel<<<dim3((Nq + 255) / 256, HEADS, Bz), 256>>>();
    // 5. output projection + bias
    gemm64_kernel<true><<<dim3(CDIM / 64, (Mq + 63) / 64), 256>>>(
        atb, proj_w, proj_b, out, Mq, CDIM, CDIM);
}

// round 2
// speedup vs baseline: 2.7670x; 2.7670x over previous
#include <cuda_runtime.h>
#include <math.h>

#define Bz    4
#define Nq    4097
#define CDIM  384
#define HEADS 8
#define HD    48
#define Msr   513

// ---------------- scratch (static device globals; no allocs allowed) --------
__device__ float g_q   [(size_t)Bz * Nq  * CDIM];     // q projection  [B,N,C]
__device__ float g_attn[(size_t)Bz * Nq  * CDIM];     // attention out [B,N,C]
__device__ float g_xr  [(size_t)Bz * Msr * CDIM];     // reduced+LN tokens
__device__ float g_kv  [(size_t)Bz * Msr * 2 * CDIM]; // kv projection

// ---------------- tf32 helpers ----------------------------------------------
__device__ __forceinline__ unsigned f2tf(float f) {
    unsigned r;
    asm("cvt.rna.tf32.f32 %0, %1;" : "=r"(r) : "f"(f));
    return r;
}

__device__ __forceinline__ void mma_tf32(float* d, const unsigned* a,
                                         unsigned b0, unsigned b1) {
    asm volatile(
        "mma.sync.aligned.m16n8k8.row.col.f32.tf32.tf32.f32 "
        "{%0,%1,%2,%3}, {%4,%5,%6,%7}, {%8,%9}, {%0,%1,%2,%3};"
        : "+f"(d[0]), "+f"(d[1]), "+f"(d[2]), "+f"(d[3])
        : "r"(a[0]), "r"(a[1]), "r"(a[2]), "r"(a[3]), "r"(b0), "r"(b1));
}

// ---------------- fused depthwise-conv(2x2x2,s2) + CLS + LayerNorm ----------
__global__ __launch_bounds__(384)
void reduce_ln_kernel(const float* __restrict__ x,
                      const float* __restrict__ sr_w,
                      const float* __restrict__ sr_b,
                      const float* __restrict__ ln_g,
                      const float* __restrict__ ln_b) {
    int m = blockIdx.x;          // 0..512 (0 = CLS)
    int b = blockIdx.y;
    int c = threadIdx.x;         // 384 channels

    float val;
    if (m == 0) {
        val = x[(size_t)(b * Nq) * CDIM + c];
    } else {
        int p  = m - 1;
        int z0 = p >> 6, z1 = (p >> 3) & 7, z2 = p & 7;
        int base = 1 + (2 * z0) * 256 + (2 * z1) * 16 + (2 * z2);
        float acc = sr_b[c];
#pragma unroll
        for (int i = 0; i < 2; i++)
#pragma unroll
            for (int j = 0; j < 2; j++)
#pragma unroll
                for (int k = 0; k < 2; k++) {
                    int tok = base + i * 256 + j * 16 + k;
                    acc = fmaf(x[(size_t)(b * Nq + tok) * CDIM + c],
                               sr_w[c * 8 + i * 4 + j * 2 + k], acc);
                }
        val = acc;
    }

    __shared__ float s_sum[12], s_sq[12];
    float v1 = val, v2 = val * val;
#pragma unroll
    for (int off = 16; off > 0; off >>= 1) {
        v1 += __shfl_xor_sync(0xffffffffu, v1, off);
        v2 += __shfl_xor_sync(0xffffffffu, v2, off);
    }
    int warp = c >> 5, lane = c & 31;
    if (lane == 0) { s_sum[warp] = v1; s_sq[warp] = v2; }
    __syncthreads();
    float tot = 0.f, totsq = 0.f;
#pragma unroll
    for (int w = 0; w < 12; w++) { tot += s_sum[w]; totsq += s_sq[w]; }
    float mu  = tot * (1.0f / CDIM);
    float var = totsq * (1.0f / CDIM) - mu * mu;
    float y = (val - mu) * rsqrtf(var + 1e-5f) * ln_g[c] + ln_b[c];
    g_xr[(size_t)(b * Msr + m) * CDIM + c] = y;
}

// ---------------- TF32 tensor-core GEMM: C[M,N] = A[M,384] @ W[N,384]^T -----
// tiles: BM=64, BN=128, BK=32; 256 threads = 8 warps (4 along M x 2 along N)
#define GK 384
template<bool HAS_BIAS>
__global__ __launch_bounds__(256)
void gemm_tc(const float* __restrict__ A, const float* __restrict__ W,
             const float* __restrict__ bias, float* __restrict__ C,
             int Md, int Nd) {
    __shared__ unsigned As[64 * 36];
    __shared__ unsigned Ws[128 * 36];
    int tid = threadIdx.x;
    int warp = tid >> 5, lane = tid & 31;
    int g = lane >> 2, t = lane & 3;
    int wm = warp & 3, wn = warp >> 2;
    int m0 = blockIdx.y * 64, n0 = blockIdx.x * 128;

    float acc[8][4] = {};

    for (int k0 = 0; k0 < GK; k0 += 32) {
        // load A tile (64x32) -> tf32 smem
#pragma unroll
        for (int i = 0; i < 2; i++) {
            int idx = tid + i * 256;          // 0..511 float4s
            int row = idx >> 3;
            int c4  = (idx & 7) * 4;
            float4 v = make_float4(0.f, 0.f, 0.f, 0.f);
            if (m0 + row < Md)
                v = *(const float4*)&A[(size_t)(m0 + row) * GK + k0 + c4];
            uint4 u = make_uint4(f2tf(v.x), f2tf(v.y), f2tf(v.z), f2tf(v.w));
            *(uint4*)&As[row * 36 + c4] = u;
        }
        // load W tile (128x32) -> tf32 smem (N dims always multiple of 128)
#pragma unroll
        for (int i = 0; i < 4; i++) {
            int idx = tid + i * 256;          // 0..1023 float4s
            int row = idx >> 3;
            int c4  = (idx & 7) * 4;
            float4 v = *(const float4*)&W[(size_t)(n0 + row) * GK + k0 + c4];
            uint4 u = make_uint4(f2tf(v.x), f2tf(v.y), f2tf(v.z), f2tf(v.w));
            *(uint4*)&Ws[row * 36 + c4] = u;
        }
        __syncthreads();

#pragma unroll
        for (int kb = 0; kb < 4; kb++) {
            unsigned a[4];
            int ar = wm * 16 + g;
            a[0] = As[ar * 36 + kb * 8 + t];
            a[1] = As[(ar + 8) * 36 + kb * 8 + t];
            a[2] = As[ar * 36 + kb * 8 + t + 4];
            a[3] = As[(ar + 8) * 36 + kb * 8 + t + 4];
#pragma unroll
            for (int nb = 0; nb < 8; nb++) {
                int bc = wn * 64 + nb * 8 + g;
                unsigned b0 = Ws[bc * 36 + kb * 8 + t];
                unsigned b1 = Ws[bc * 36 + kb * 8 + t + 4];
                mma_tf32(acc[nb], a, b0, b1);
            }
        }
        __syncthreads();
    }

    // store
#pragma unroll
    for (int nb = 0; nb < 8; nb++) {
        int col = n0 + wn * 64 + nb * 8 + 2 * t;
        float bx = 0.f, by = 0.f;
        if (HAS_BIAS) { bx = bias[col]; by = bias[col + 1]; }
        int r = m0 + wm * 16 + g;
        if (r < Md) {
            float2 v = make_float2(acc[nb][0] + bx, acc[nb][1] + by);
            *(float2*)&C[(size_t)r * Nd + col] = v;
        }
        if (r + 8 < Md) {
            float2 v = make_float2(acc[nb][2] + bx, acc[nb][3] + by);
            *(float2*)&C[(size_t)(r + 8) * Nd + col] = v;
        }
    }
}

// ---------------- TF32 tensor-core flash attention --------------------------
// CTA: 64 queries, 4 warps x 16 rows; key chunks of 64 staged in smem
#define KSTR 50
#define VSTR 56
#define PSTR 68
__global__ __launch_bounds__(128)
void attn_tc_kernel() {
    __shared__ unsigned ks[64 * KSTR];
    __shared__ unsigned vs[64 * VSTR];
    __shared__ unsigned ps[4 * 16 * PSTR];

    int tid = threadIdx.x;
    int warp = tid >> 5, lane = tid & 31;
    int g = lane >> 2, t = lane & 3;
    int h = blockIdx.y, b = blockIdx.z;
    int qbase = blockIdx.x * 64 + warp * 16;
    int r0 = qbase + g, r1 = r0 + 8;
    const float scale = rsqrtf((float)HD);

    // Q fragments (scaled, tf32)
    unsigned qf[6][4];
    const float* qp = g_q + (size_t)(b * Nq) * CDIM + h * HD;
#pragma unroll
    for (int kb = 0; kb < 6; kb++) {
        int c0 = kb * 8 + t;
        float a0 = (r0 < Nq) ? qp[(size_t)r0 * CDIM + c0] : 0.f;
        float a1 = (r1 < Nq) ? qp[(size_t)r1 * CDIM + c0] : 0.f;
        float a2 = (r0 < Nq) ? qp[(size_t)r0 * CDIM + c0 + 4] : 0.f;
        float a3 = (r1 < Nq) ? qp[(size_t)r1 * CDIM + c0 + 4] : 0.f;
        qf[kb][0] = f2tf(a0 * scale);
        qf[kb][1] = f2tf(a1 * scale);
        qf[kb][2] = f2tf(a2 * scale);
        qf[kb][3] = f2tf(a3 * scale);
    }

    float o[6][4] = {};
    float mx0 = -1e30f, mx1 = -1e30f, l0 = 0.f, l1 = 0.f;
    unsigned* pw = ps + warp * 16 * PSTR;

    for (int m0 = 0; m0 < Msr; m0 += 64) {
        // cooperative K/V load (tf32, zero-padded)
        for (int u = tid; u < 64 * 12; u += 128) {
            int key = u / 12;
            int d4  = (u % 12) * 4;
            float4 kv4 = make_float4(0.f, 0.f, 0.f, 0.f);
            float4 vv4 = make_float4(0.f, 0.f, 0.f, 0.f);
            if (m0 + key < Msr) {
                size_t base = (size_t)(b * Msr + m0 + key) * (2 * CDIM) + h * HD + d4;
                kv4 = *(const float4*)&g_kv[base];
                vv4 = *(const float4*)&g_kv[base + CDIM];
            }
            unsigned* kd = &ks[key * KSTR + d4];
            kd[0] = f2tf(kv4.x); kd[1] = f2tf(kv4.y);
            kd[2] = f2tf(kv4.z); kd[3] = f2tf(kv4.w);
            unsigned* vd = &vs[key * VSTR + d4];
            vd[0] = f2tf(vv4.x); vd[1] = f2tf(vv4.y);
            vd[2] = f2tf(vv4.z); vd[3] = f2tf(vv4.w);
        }
        __syncthreads();

        // S = Q @ K^T
        float s[8][4];
#pragma unroll
        for (int nb = 0; nb < 8; nb++) {
            s[nb][0] = s[nb][1] = s[nb][2] = s[nb][3] = 0.f;
#pragma unroll
            for (int kb = 0; kb < 6; kb++) {
                unsigned b0 = ks[(nb * 8 + g) * KSTR + kb * 8 + t];
                unsigned b1 = ks[(nb * 8 + g) * KSTR + kb * 8 + t + 4];
                mma_tf32(s[nb], qf[kb], b0, b1);
            }
        }

        // mask invalid keys + chunk row max
        float cm0 = -1e30f, cm1 = -1e30f;
#pragma unroll
        for (int nb = 0; nb < 8; nb++) {
            int key = m0 + nb * 8 + 2 * t;
            if (key >= Msr)     s[nb][0] = s[nb][2] = -1e30f;
            if (key + 1 >= Msr) s[nb][1] = s[nb][3] = -1e30f;
            cm0 = fmaxf(cm0, fmaxf(s[nb][0], s[nb][1]));
            cm1 = fmaxf(cm1, fmaxf(s[nb][2], s[nb][3]));
        }
        cm0 = fmaxf(cm0, __shfl_xor_sync(0xffffffffu, cm0, 1));
        cm0 = fmaxf(cm0, __shfl_xor_sync(0xffffffffu, cm0, 2));
        cm1 = fmaxf(cm1, __shfl_xor_sync(0xffffffffu, cm1, 1));
        cm1 = fmaxf(cm1, __shfl_xor_sync(0xffffffffu, cm1, 2));

        float nm0 = fmaxf(mx0, cm0), nm1 = fmaxf(mx1, cm1);
        float corr0 = __expf(mx0 - nm0), corr1 = __expf(mx1 - nm1);
        mx0 = nm0; mx1 = nm1;

        // P = exp(S - m), write to smem (tf32), accumulate row sums
        float sum0 = 0.f, sum1 = 0.f;
#pragma unroll
        for (int nb = 0; nb < 8; nb++) {
            float p0 = __expf(s[nb][0] - nm0);
            float p1 = __expf(s[nb][1] - nm0);
            float p2 = __expf(s[nb][2] - nm1);
            float p3 = __expf(s[nb][3] - nm1);
            sum0 += p0 + p1; sum1 += p2 + p3;
            int col = nb * 8 + 2 * t;
            pw[g * PSTR + col]           = f2tf(p0);
            pw[g * PSTR + col + 1]       = f2tf(p1);
            pw[(g + 8) * PSTR + col]     = f2tf(p2);
            pw[(g + 8) * PSTR + col + 1] = f2tf(p3);
        }
        sum0 += __shfl_xor_sync(0xffffffffu, sum0, 1);
        sum0 += __shfl_xor_sync(0xffffffffu, sum0, 2);
        sum1 += __shfl_xor_sync(0xffffffffu, sum1, 1);
        sum1 += __shfl_xor_sync(0xffffffffu, sum1, 2);
        l0 = l0 * corr0 + sum0;
        l1 = l1 * corr1 + sum1;

        // rescale running output
#pragma unroll
        for (int nb = 0; nb < 6; nb++) {
            o[nb][0] *= corr0; o[nb][1] *= corr0;
            o[nb][2] *= corr1; o[nb][3] *= corr1;
        }
        __syncwarp();

        // O += P @ V
#pragma unroll
        for (int kb = 0; kb < 8; kb++) {
            unsigned a[4];
            a[0] = pw[g * PSTR + kb * 8 + t];
            a[1] = pw[(g + 8) * PSTR + kb * 8 + t];
            a[2] = pw[g * PSTR + kb * 8 + t + 4];
            a[3] = pw[(g + 8) * PSTR + kb * 8 + t + 4];
#pragma unroll
            for (int nb = 0; nb < 6; nb++) {
                unsigned b0 = vs[(kb * 8 + t) * VSTR + nb * 8 + g];
                unsigned b1 = vs[(kb * 8 + t + 4) * VSTR + nb * 8 + g];
                mma_tf32(o[nb], a, b0, b1);
            }
        }
        __syncthreads();
    }

    // epilogue
    float i0 = 1.f / l0, i1 = 1.f / l1;
    float* op = g_attn + (size_t)(b * Nq) * CDIM + h * HD;
#pragma unroll
    for (int nb = 0; nb < 6; nb++) {
        int col = nb * 8 + 2 * t;
        if (r0 < Nq) {
            float2 v = make_float2(o[nb][0] * i0, o[nb][1] * i0);
            *(float2*)&op[(size_t)r0 * CDIM + col] = v;
        }
        if (r1 < Nq) {
            float2 v = make_float2(o[nb][2] * i1, o[nb][3] * i1);
            *(float2*)&op[(size_t)r1 * CDIM + col] = v;
        }
    }
}

// ---------------- launcher ---------------------------------------------------
extern "C" void kernel_launch(void* const* d_in, const int* in_sizes, int n_in,
                              void* d_out, int out_size) {
    const float* x      = (const float*)d_in[0];
    const float* q_w    = (const float*)d_in[1];
    const float* kv_w   = (const float*)d_in[2];
    const float* proj_w = (const float*)d_in[3];
    const float* proj_b = (const float*)d_in[4];
    const float* sr_w   = (const float*)d_in[5];
    const float* sr_b   = (const float*)d_in[6];
    const float* ln_g   = (const float*)d_in[7];
    const float* ln_b   = (const float*)d_in[8];
    float* out = (float*)d_out;

    float *qb, *xrb, *kvb, *atb;
    cudaGetSymbolAddress((void**)&qb,  g_q);
    cudaGetSymbolAddress((void**)&xrb, g_xr);
    cudaGetSymbolAddress((void**)&kvb, g_kv);
    cudaGetSymbolAddress((void**)&atb, g_attn);

    const int Mq = Bz * Nq;        // 16388
    const int Mr = Bz * Msr;       // 2052

    // 1. reduced tokens + LN
    reduce_ln_kernel<<<dim3(Msr, Bz), 384>>>(x, sr_w, sr_b, ln_g, ln_b);
    // 2. kv projection: [2052,384] @ [768,384]^T
    gemm_tc<false><<<dim3(768 / 128, (Mr + 63) / 64), 256>>>(
        xrb, kv_w, nullptr, kvb, Mr, 2 * CDIM);
    // 3. q projection: [16388,384] @ [384,384]^T
    gemm_tc<false><<<dim3(CDIM / 128, (Mq + 63) / 64), 256>>>(
        x, q_w, nullptr, qb, Mq, CDIM);
    // 4. attention (tensor-core flash)
    attn_tc_kernel<<<dim3((Nq + 63) / 64, HEADS, Bz), 128>>>();
    // 5. output projection + bias
    gemm_tc<true><<<dim3(CDIM / 128, (Mq + 63) / 64), 256>>>(
        atb, proj_w, proj_b, out, Mq, CDIM);
}